// round 12
// baseline (speedup 1.0000x reference)
#include <cuda_runtime.h>
#include <cuda_bf16.h>
#include <math.h>

__device__ __forceinline__ float sg(float x) { return 1.f / (1.f + __expf(-x)); }

// ============================================================================
// Cold path: warp-collective exact solver for one uncertified matrix.
// Householder tridiagonalization in registers + Sturm multisection lambda_2.
// Executed by warp 0 of the flagging CTA only (essentially never on this
// distribution). May spill under the reg cap — correctness only matters here.
// ============================================================================
__device__ __noinline__ void solve_one_warp(
    const float* __restrict__ Eb, float* __restrict__ out, int B, int lane,
    float* __restrict__ sv, float* __restrict__ sw_,
    float* __restrict__ sdd, float* __restrict__ see)
{
    const int rL = lane, rH = lane + 32;
    float aL[64], aH[64];

    float degL = 0.f, degH = 0.f, dsL = 0.f, dsH = 0.f;
    #pragma unroll
    for (int j0 = 0; j0 < 64; j0 += 4) {
        float4 eL = *(const float4*)(Eb + (size_t)rL * 64 + j0);
        float4 eH = *(const float4*)(Eb + (size_t)rH * 64 + j0);
        float s;
        s = sg(eL.x); degL += s; if (j0+0 <  rL) aL[j0+0] = -s; if (j0+0 == rL) dsL = s;
        s = sg(eL.y); degL += s; if (j0+1 <  rL) aL[j0+1] = -s; if (j0+1 == rL) dsL = s;
        s = sg(eL.z); degL += s; if (j0+2 <  rL) aL[j0+2] = -s; if (j0+2 == rL) dsL = s;
        s = sg(eL.w); degL += s; if (j0+3 <  rL) aL[j0+3] = -s; if (j0+3 == rL) dsL = s;
        s = sg(eH.x); degH += s; if (j0+0 <  rH) aH[j0+0] = -s; if (j0+0 == rH) dsH = s;
        s = sg(eH.y); degH += s; if (j0+1 <  rH) aH[j0+1] = -s; if (j0+1 == rH) dsH = s;
        s = sg(eH.z); degH += s; if (j0+2 <  rH) aH[j0+2] = -s; if (j0+2 == rH) dsH = s;
        s = sg(eH.w); degH += s; if (j0+3 <  rH) aH[j0+3] = -s; if (j0+3 == rH) dsH = s;
    }
    #pragma unroll
    for (int j = 1; j < 64; j++) {
        float eu = Eb[(size_t)j * 64 + rL];
        if (j > rL) aL[j] = -sg(eu);
        if (j >= 33) {
            float eu2 = Eb[(size_t)j * 64 + rH];
            if (j > rH) aH[j] = -sg(eu2);
        }
    }
    {
        float dL = degL - dsL, dH = degH - dsH;
        #pragma unroll
        for (int j = 0; j < 64; j++) {
            if (j == rL) aL[j] = dL;
            if (j == rH) aH[j] = dH;
        }
    }

    float xiL = aL[0];
    float xiH = aH[0];

    for (int k = 0; k < 62; k++) {
        const int m0 = k + 1;

        float cL = (rL >= m0) ? xiL : 0.f;
        float cH = (rH >= m0) ? xiH : 0.f;
        float sig = cL * cL + cH * cH;
        #pragma unroll
        for (int o = 16; o > 0; o >>= 1) sig += __shfl_xor_sync(0xffffffffu, sig, o);

        float cand = (m0 < 32) ? xiL : xiH;
        float x0 = __shfl_sync(0xffffffffu, cand, m0 & 31);

        float normx = sqrtf(sig);
        bool  skip  = (normx < 1e-18f);
        float alpha = (x0 >= 0.f) ? -normx : normx;
        float beta  = skip ? 0.f : 1.f / (normx * (normx + fabsf(x0)));

        if (lane == 0) see[k] = skip ? 0.f : alpha;
        if (rL == k)   sdd[k] = xiL;
        if (rH == k)   sdd[k] = xiH;

        float vL = (rL > m0) ? xiL : ((rL == m0) ? (x0 - alpha) : 0.f);
        float vH = (rH > m0) ? xiH : ((rH == m0) ? (x0 - alpha) : 0.f);
        sv[rL] = vL;
        sv[rH] = vH;
        __syncwarp();

        const int c0 = m0 >> 4;
        float pL0 = 0.f, pL1 = 0.f, pH0 = 0.f, pH1 = 0.f;
        #pragma unroll
        for (int c = 0; c < 4; c++) {
            if (c >= c0) {
                #pragma unroll
                for (int u = 0; u < 16; u += 4) {
                    const int j = 16 * c + u;
                    float4 v4 = *(const float4*)&sv[j];
                    pL0 += aL[j]     * v4.x + aL[j + 1] * v4.y;
                    pL1 += aL[j + 2] * v4.z + aL[j + 3] * v4.w;
                    pH0 += aH[j]     * v4.x + aH[j + 1] * v4.y;
                    pH1 += aH[j + 2] * v4.z + aH[j + 3] * v4.w;
                }
            }
        }
        float pL = (rL >= m0) ? (pL0 + pL1) * beta : 0.f;
        float pH = (rH >= m0) ? (pH0 + pH1) * beta : 0.f;

        float Ks = vL * pL + vH * pH;
        #pragma unroll
        for (int o = 16; o > 0; o >>= 1) Ks += __shfl_xor_sync(0xffffffffu, Ks, o);
        float K  = 0.5f * Ks;
        float wL = pL - K * vL;
        float wH = pH - K * vH;
        __syncwarp();
        sw_[rL] = wL;
        sw_[rH] = wH;
        __syncwarp();

        float nL = 0.f, nH = 0.f;
        #pragma unroll
        for (int c = 0; c < 4; c++) {
            if (c >= c0) {
                #pragma unroll
                for (int u = 0; u < 16; u += 4) {
                    const int j = 16 * c + u;
                    float4 v4 = *(const float4*)&sv[j];
                    float4 w4 = *(const float4*)&sw_[j];
                    float x;
                    x = aL[j]   - (vL * w4.x + wL * v4.x); aL[j]   = x; if (j     == m0) nL = x;
                    x = aL[j+1] - (vL * w4.y + wL * v4.y); aL[j+1] = x; if (j + 1 == m0) nL = x;
                    x = aL[j+2] - (vL * w4.z + wL * v4.z); aL[j+2] = x; if (j + 2 == m0) nL = x;
                    x = aL[j+3] - (vL * w4.w + wL * v4.w); aL[j+3] = x; if (j + 3 == m0) nL = x;
                    x = aH[j]   - (vH * w4.x + wH * v4.x); aH[j]   = x; if (j     == m0) nH = x;
                    x = aH[j+1] - (vH * w4.y + wH * v4.y); aH[j+1] = x; if (j + 1 == m0) nH = x;
                    x = aH[j+2] - (vH * w4.z + wH * v4.z); aH[j+2] = x; if (j + 2 == m0) nH = x;
                    x = aH[j+3] - (vH * w4.w + wH * v4.w); aH[j+3] = x; if (j + 3 == m0) nH = x;
                }
            }
        }
        xiL = nL;
        xiH = nH;
        __syncwarp();
    }

    if (rH == 62) sdd[62] = xiH;
    if (rH == 63) {
        see[62] = xiH;
        sdd[63] = aH[63];
        see[63] = 0.f;
    }
    __syncwarp();

    sw_[rL] = see[rL] * see[rL];
    sw_[rH] = see[rH] * see[rH];
    __syncwarp();

    float dLv = sdd[rL], dHv = sdd[rH];
    float radL = ((rL > 0) ? fabsf(see[rL - 1]) : 0.f) + fabsf(see[rL]);
    float radH = fabsf(see[rH - 1]) + ((rH < 63) ? fabsf(see[rH]) : 0.f);
    float lo = fminf(dLv - radL, dHv - radH);
    float hi = fmaxf(dLv + radL, dHv + radH);
    #pragma unroll
    for (int o = 16; o > 0; o >>= 1) {
        lo = fminf(lo, __shfl_xor_sync(0xffffffffu, lo, o));
        hi = fmaxf(hi, __shfl_xor_sync(0xffffffffu, hi, o));
    }

    #pragma unroll 1
    for (int round = 0; round < 5; round++) {
        float stepw = (hi - lo) * (1.f / 33.f);
        float x = lo + stepw * (float)(lane + 1);
        int cnt = 0;
        float q = sdd[0] - x;
        if (q < 0.f) cnt++;
        #pragma unroll 1
        for (int i = 1; i < 64; i++) {
            float denom = q;
            if (fabsf(denom) < 1e-25f) denom = (denom < 0.f) ? -1e-25f : 1e-25f;
            q = (sdd[i] - x) - __fdividef(sw_[i - 1], denom);
            if (q < 0.f) cnt++;
        }
        unsigned bal = __ballot_sync(0xffffffffu, cnt >= 2);
        if (bal == 0u) {
            lo = lo + stepw * 32.f;
        } else {
            int j = __ffs(bal) - 1;
            float nhi = lo + stepw * (float)(j + 1);
            float nlo = (j > 0) ? (lo + stepw * (float)j) : lo;
            hi = nhi; lo = nlo;
        }
    }
    if (lane == 0) {
        float lam2 = 0.5f * (lo + hi);
        float p = 0.1f - lam2;
        if (p > 0.f) atomicAdd(out, p / (float)B);
    }
}

// ============================================================================
// Fused kernel: transcendental-free certificate that lambda_2 >= 0.1; if the
// certificate fails (rare/never), warp 0 of the SAME CTA runs the exact
// eigensolver in place and atomically adds relu(0.1-lambda2)/B to out.
//
// Certificate: M = lower-symmetrized (diag(deg) - sigmoid(E));
// P = (M - 0.1I) + 0.5*ones*ones^T; lambda_1(P) <= lambda_2(M - 0.1I)
// (positive rank-1 interlacing). Gershgorin on P with piecewise-linear
// sigmoid bounds:
//   deg_t >= sum_j clamp(0.5 + E[t][j]/4, 0, 0.5)
//   |0.5 - sigma(x)| <= min(|x|/4, 0.5),  sigma_tt <= 1
// min_t bound_t >= 0 (with fp slack)  =>  penalty contribution is exactly 0.
// ============================================================================
__global__ void __launch_bounds__(128, 8)
spectral_fused_kernel(const float* __restrict__ E, float* __restrict__ out, int B)
{
    const int b = blockIdx.x;
    if (b >= B) return;
    const int t = threadIdx.x;
    const int q = t & 15;    // column quad: columns 4q..4q+3
    const int g = t >> 4;    // row group 0..7: rows 8i+g

    __shared__ float P[64][17][2];   // [row][q][{deg,rad}]
    __shared__ float colP[8][64];    // [g][col] partial column radii
    __shared__ float warpmin[4];
    __shared__ int   sneed;
    __shared__ __align__(16) float ssv[64], ssw[64], ssdd[64], ssee[64];

    const float* Eb = E + (size_t)b * 4096;
    const float4* E4 = (const float4*)Eb;
    const int c0 = 4 * q;

    float col0 = 0.f, col1 = 0.f, col2 = 0.f, col3 = 0.f;

    #pragma unroll
    for (int i = 0; i < 8; i++) {
        float4 v = E4[i * 128 + t];          // fully coalesced
        const int r = 8 * i + g;
        float dacc = 0.f, racc = 0.f;
        float t1, m;

        t1 = fmaf(0.25f, v.x, 0.5f);
        dacc += fminf(fmaxf(t1, 0.f), 0.5f);
        m = fminf(fabsf(t1 - 0.5f), 0.5f);
        if (r > c0 + 0) { racc += m; col0 += m; }

        t1 = fmaf(0.25f, v.y, 0.5f);
        dacc += fminf(fmaxf(t1, 0.f), 0.5f);
        m = fminf(fabsf(t1 - 0.5f), 0.5f);
        if (r > c0 + 1) { racc += m; col1 += m; }

        t1 = fmaf(0.25f, v.z, 0.5f);
        dacc += fminf(fmaxf(t1, 0.f), 0.5f);
        m = fminf(fabsf(t1 - 0.5f), 0.5f);
        if (r > c0 + 2) { racc += m; col2 += m; }

        t1 = fmaf(0.25f, v.w, 0.5f);
        dacc += fminf(fmaxf(t1, 0.f), 0.5f);
        m = fminf(fabsf(t1 - 0.5f), 0.5f);
        if (r > c0 + 3) { racc += m; col3 += m; }

        P[r][q][0] = dacc;
        P[r][q][1] = racc;
    }
    colP[g][c0 + 0] = col0;
    colP[g][c0 + 1] = col1;
    colP[g][c0 + 2] = col2;
    colP[g][c0 + 3] = col3;
    __syncthreads();

    float bound = 1e30f;
    if (t < 64) {
        float dsum = 0.f, rsum = 0.f;
        #pragma unroll
        for (int qq = 0; qq < 16; qq++) {
            dsum += P[t][qq][0];
            rsum += P[t][qq][1];
        }
        #pragma unroll
        for (int gg = 0; gg < 8; gg++) rsum += colP[gg][t];
        bound = dsum - 0.6f - rsum;
    }
    #pragma unroll
    for (int o = 16; o > 0; o >>= 1)
        bound = fminf(bound, __shfl_xor_sync(0xffffffffu, bound, o));
    if ((t & 31) == 0) warpmin[t >> 5] = bound;
    __syncthreads();
    if (t == 0) {
        float mn = fminf(fminf(warpmin[0], warpmin[1]),
                         fminf(warpmin[2], warpmin[3]));
        sneed = (mn < 0.05f) ? 1 : 0;        // 0.05 = fp-rounding slack
    }
    __syncthreads();

    // Cold path: exact solve by warp 0 of this CTA (certificate failed).
    if (sneed && t < 32) {
        solve_one_warp(Eb, out, B, t, ssv, ssw, ssdd, ssee);
    }
}

extern "C" void kernel_launch(void* const* d_in, const int* in_sizes, int n_in,
                              void* d_out, int out_size)
{
    const float* E = (const float*)d_in[0];
    int B = in_sizes[0] / 4096;

    cudaMemsetAsync(d_out, 0, sizeof(float));     // out = 0; rare path adds terms
    spectral_fused_kernel<<<B, 128>>>(E, (float*)d_out, B);
}

// round 13
// speedup vs baseline: 1.0409x; 1.0409x over previous
#include <cuda_runtime.h>
#include <cuda_bf16.h>
#include <math.h>

#define MAXB 8192

__device__ int g_cnt = 0;          // zero-init; reset by fallback kernel each run
__device__ int g_list[MAXB];

__device__ __forceinline__ float sg(float x) { return 1.f / (1.f + __expf(-x)); }

// ============================================================================
// Kernel 1: transcendental-free certificate that lambda_2 >= 0.1, single pass.
//
// M = lower-symmetrized (diag(deg) - sigmoid(E));  P = (M - 0.1I) + 0.5*ones*ones^T.
// lambda_1(P) <= lambda_2(M - 0.1I)  (positive rank-1 interlacing).
// Gershgorin row bound on P with piecewise-linear sigmoid bounds:
//   deg_t >= sum_j clamp(0.5 + E[t][j]/4, 0, 0.5)
//   |0.5 - sigma(x)| <= min(|x|/4, 0.5),  sigma_tt <= 1
// bound_t = deg_lo_t - 0.6 - rad_t;  min_t bound_t >= 0 (with slack) => penalty 0.
// Failures (essentially never) are appended to g_list for the exact solver.
//
// Layout: 128 threads/matrix; thread (q = t&15, g = t>>4) handles columns
// 4q..4q+3 of rows 8i+g. deg - row_rad folds into ONE accumulator e (linear),
// reduced across the 16 q-lanes by shfl butterflies (no big smem array).
// ============================================================================
__global__ void __launch_bounds__(128, 9)
certify_kernel(const float* __restrict__ E, int B)
{
    const int b = blockIdx.x;
    if (b >= B) return;
    const int t  = threadIdx.x;
    const int q  = t & 15;
    const int g  = t >> 4;
    const int c0 = 4 * q;

    __shared__ float colP[8][64];    // [g][col] partial column radii
    __shared__ float rowB[64];       // per-row (deg_lo - row_rad - 0.6)
    __shared__ float warpmin[4];

    const float4* E4 = (const float4*)(E + (size_t)b * 4096);

    float e[8];                      // per-row-i: degterm - rowrad partials
    float col0 = 0.f, col1 = 0.f, col2 = 0.f, col3 = 0.f;

    #pragma unroll
    for (int h = 0; h < 2; h++) {
        float4 v[4];
        #pragma unroll
        for (int u = 0; u < 4; u++) v[u] = E4[(4 * h + u) * 128 + t];  // MLP=4
        #pragma unroll
        for (int u = 0; u < 4; u++) {
            const int i = 4 * h + u;
            const int r = 8 * i + g;
            float acc = 0.f, uu, m;

            uu = 0.25f * v[u].x;
            acc += fminf(fmaxf(uu + 0.5f, 0.f), 0.5f);
            m = fminf(fabsf(uu), 0.5f);
            if (r > c0 + 0) { acc -= m; col0 += m; }

            uu = 0.25f * v[u].y;
            acc += fminf(fmaxf(uu + 0.5f, 0.f), 0.5f);
            m = fminf(fabsf(uu), 0.5f);
            if (r > c0 + 1) { acc -= m; col1 += m; }

            uu = 0.25f * v[u].z;
            acc += fminf(fmaxf(uu + 0.5f, 0.f), 0.5f);
            m = fminf(fabsf(uu), 0.5f);
            if (r > c0 + 2) { acc -= m; col2 += m; }

            uu = 0.25f * v[u].w;
            acc += fminf(fmaxf(uu + 0.5f, 0.f), 0.5f);
            m = fminf(fabsf(uu), 0.5f);
            if (r > c0 + 3) { acc -= m; col3 += m; }

            e[i] = acc;
        }
    }

    // Butterfly over the 16 q-lanes (xor<16 stays within the half-warp = one g)
    #pragma unroll
    for (int o = 1; o < 16; o <<= 1) {
        #pragma unroll
        for (int i = 0; i < 8; i++)
            e[i] += __shfl_xor_sync(0xffffffffu, e[i], o);
    }

    // Lane q<8 publishes row 8q+g (static-index select from e[])
    if (q < 8) {
        float es = 0.f;
        #pragma unroll
        for (int i = 0; i < 8; i++)
            if (q == i) es = e[i];
        rowB[8 * q + g] = es - 0.6f;
    }
    colP[g][c0 + 0] = col0;
    colP[g][c0 + 1] = col1;
    colP[g][c0 + 2] = col2;
    colP[g][c0 + 3] = col3;
    __syncthreads();

    float bound = 1e30f;
    if (t < 64) {
        float cs = 0.f;
        #pragma unroll
        for (int gg = 0; gg < 8; gg++) cs += colP[gg][t];
        bound = rowB[t] - cs;
    }
    #pragma unroll
    for (int o = 16; o > 0; o >>= 1)
        bound = fminf(bound, __shfl_xor_sync(0xffffffffu, bound, o));
    if ((t & 31) == 0) warpmin[t >> 5] = bound;
    __syncthreads();
    if (t == 0) {
        float mn = fminf(fminf(warpmin[0], warpmin[1]),
                         fminf(warpmin[2], warpmin[3]));
        if (mn < 0.05f) {                       // 0.05 = fp-rounding slack
            int idx = atomicAdd(&g_cnt, 1);
            if (idx < MAXB) g_list[idx] = b;
        }
    }
}

// ============================================================================
// Cold path: warp-collective exact solver for one uncertified matrix.
// Householder tridiagonalization in registers + Sturm multisection lambda_2.
// Returns relu(0.1 - lambda_2)/B on lane 0.
// ============================================================================
__device__ __noinline__ float solve_one_warp(
    const float* __restrict__ Eb, int B, int lane,
    float* __restrict__ sv, float* __restrict__ sw_,
    float* __restrict__ sdd, float* __restrict__ see)
{
    const int rL = lane, rH = lane + 32;
    float aL[64], aH[64];

    float degL = 0.f, degH = 0.f, dsL = 0.f, dsH = 0.f;
    #pragma unroll
    for (int j0 = 0; j0 < 64; j0 += 4) {
        float4 eL = *(const float4*)(Eb + (size_t)rL * 64 + j0);
        float4 eH = *(const float4*)(Eb + (size_t)rH * 64 + j0);
        float s;
        s = sg(eL.x); degL += s; if (j0+0 <  rL) aL[j0+0] = -s; if (j0+0 == rL) dsL = s;
        s = sg(eL.y); degL += s; if (j0+1 <  rL) aL[j0+1] = -s; if (j0+1 == rL) dsL = s;
        s = sg(eL.z); degL += s; if (j0+2 <  rL) aL[j0+2] = -s; if (j0+2 == rL) dsL = s;
        s = sg(eL.w); degL += s; if (j0+3 <  rL) aL[j0+3] = -s; if (j0+3 == rL) dsL = s;
        s = sg(eH.x); degH += s; if (j0+0 <  rH) aH[j0+0] = -s; if (j0+0 == rH) dsH = s;
        s = sg(eH.y); degH += s; if (j0+1 <  rH) aH[j0+1] = -s; if (j0+1 == rH) dsH = s;
        s = sg(eH.z); degH += s; if (j0+2 <  rH) aH[j0+2] = -s; if (j0+2 == rH) dsH = s;
        s = sg(eH.w); degH += s; if (j0+3 <  rH) aH[j0+3] = -s; if (j0+3 == rH) dsH = s;
    }
    #pragma unroll
    for (int j = 1; j < 64; j++) {
        float eu = Eb[(size_t)j * 64 + rL];
        if (j > rL) aL[j] = -sg(eu);
        if (j >= 33) {
            float eu2 = Eb[(size_t)j * 64 + rH];
            if (j > rH) aH[j] = -sg(eu2);
        }
    }
    {
        float dL = degL - dsL, dH = degH - dsH;
        #pragma unroll
        for (int j = 0; j < 64; j++) {
            if (j == rL) aL[j] = dL;
            if (j == rH) aH[j] = dH;
        }
    }

    float xiL = aL[0];
    float xiH = aH[0];

    for (int k = 0; k < 62; k++) {
        const int m0 = k + 1;

        float cL = (rL >= m0) ? xiL : 0.f;
        float cH = (rH >= m0) ? xiH : 0.f;
        float sig = cL * cL + cH * cH;
        #pragma unroll
        for (int o = 16; o > 0; o >>= 1) sig += __shfl_xor_sync(0xffffffffu, sig, o);

        float cand = (m0 < 32) ? xiL : xiH;
        float x0 = __shfl_sync(0xffffffffu, cand, m0 & 31);

        float normx = sqrtf(sig);
        bool  skip  = (normx < 1e-18f);
        float alpha = (x0 >= 0.f) ? -normx : normx;
        float beta  = skip ? 0.f : 1.f / (normx * (normx + fabsf(x0)));

        if (lane == 0) see[k] = skip ? 0.f : alpha;
        if (rL == k)   sdd[k] = xiL;
        if (rH == k)   sdd[k] = xiH;

        float vL = (rL > m0) ? xiL : ((rL == m0) ? (x0 - alpha) : 0.f);
        float vH = (rH > m0) ? xiH : ((rH == m0) ? (x0 - alpha) : 0.f);
        sv[rL] = vL;
        sv[rH] = vH;
        __syncwarp();

        const int c0 = m0 >> 4;
        float pL0 = 0.f, pL1 = 0.f, pH0 = 0.f, pH1 = 0.f;
        #pragma unroll
        for (int c = 0; c < 4; c++) {
            if (c >= c0) {
                #pragma unroll
                for (int u = 0; u < 16; u += 4) {
                    const int j = 16 * c + u;
                    float4 v4 = *(const float4*)&sv[j];
                    pL0 += aL[j]     * v4.x + aL[j + 1] * v4.y;
                    pL1 += aL[j + 2] * v4.z + aL[j + 3] * v4.w;
                    pH0 += aH[j]     * v4.x + aH[j + 1] * v4.y;
                    pH1 += aH[j + 2] * v4.z + aH[j + 3] * v4.w;
                }
            }
        }
        float pL = (rL >= m0) ? (pL0 + pL1) * beta : 0.f;
        float pH = (rH >= m0) ? (pH0 + pH1) * beta : 0.f;

        float Ks = vL * pL + vH * pH;
        #pragma unroll
        for (int o = 16; o > 0; o >>= 1) Ks += __shfl_xor_sync(0xffffffffu, Ks, o);
        float K  = 0.5f * Ks;
        float wL = pL - K * vL;
        float wH = pH - K * vH;
        __syncwarp();
        sw_[rL] = wL;
        sw_[rH] = wH;
        __syncwarp();

        float nL = 0.f, nH = 0.f;
        #pragma unroll
        for (int c = 0; c < 4; c++) {
            if (c >= c0) {
                #pragma unroll
                for (int u = 0; u < 16; u += 4) {
                    const int j = 16 * c + u;
                    float4 v4 = *(const float4*)&sv[j];
                    float4 w4 = *(const float4*)&sw_[j];
                    float x;
                    x = aL[j]   - (vL * w4.x + wL * v4.x); aL[j]   = x; if (j     == m0) nL = x;
                    x = aL[j+1] - (vL * w4.y + wL * v4.y); aL[j+1] = x; if (j + 1 == m0) nL = x;
                    x = aL[j+2] - (vL * w4.z + wL * v4.z); aL[j+2] = x; if (j + 2 == m0) nL = x;
                    x = aL[j+3] - (vL * w4.w + wL * v4.w); aL[j+3] = x; if (j + 3 == m0) nL = x;
                    x = aH[j]   - (vH * w4.x + wH * v4.x); aH[j]   = x; if (j     == m0) nH = x;
                    x = aH[j+1] - (vH * w4.y + wH * v4.y); aH[j+1] = x; if (j + 1 == m0) nH = x;
                    x = aH[j+2] - (vH * w4.z + wH * v4.z); aH[j+2] = x; if (j + 2 == m0) nH = x;
                    x = aH[j+3] - (vH * w4.w + wH * v4.w); aH[j+3] = x; if (j + 3 == m0) nH = x;
                }
            }
        }
        xiL = nL;
        xiH = nH;
        __syncwarp();
    }

    if (rH == 62) sdd[62] = xiH;
    if (rH == 63) {
        see[62] = xiH;
        sdd[63] = aH[63];
        see[63] = 0.f;
    }
    __syncwarp();

    sw_[rL] = see[rL] * see[rL];
    sw_[rH] = see[rH] * see[rH];
    __syncwarp();

    float dLv = sdd[rL], dHv = sdd[rH];
    float radL = ((rL > 0) ? fabsf(see[rL - 1]) : 0.f) + fabsf(see[rL]);
    float radH = fabsf(see[rH - 1]) + ((rH < 63) ? fabsf(see[rH]) : 0.f);
    float lo = fminf(dLv - radL, dHv - radH);
    float hi = fmaxf(dLv + radL, dHv + radH);
    #pragma unroll
    for (int o = 16; o > 0; o >>= 1) {
        lo = fminf(lo, __shfl_xor_sync(0xffffffffu, lo, o));
        hi = fmaxf(hi, __shfl_xor_sync(0xffffffffu, hi, o));
    }

    #pragma unroll 1
    for (int round = 0; round < 5; round++) {
        float stepw = (hi - lo) * (1.f / 33.f);
        float x = lo + stepw * (float)(lane + 1);
        int cnt = 0;
        float qq = sdd[0] - x;
        if (qq < 0.f) cnt++;
        #pragma unroll 1
        for (int i = 1; i < 64; i++) {
            float denom = qq;
            if (fabsf(denom) < 1e-25f) denom = (denom < 0.f) ? -1e-25f : 1e-25f;
            qq = (sdd[i] - x) - __fdividef(sw_[i - 1], denom);
            if (qq < 0.f) cnt++;
        }
        unsigned bal = __ballot_sync(0xffffffffu, cnt >= 2);
        if (bal == 0u) {
            lo = lo + stepw * 32.f;
        } else {
            int j = __ffs(bal) - 1;
            float nhi = lo + stepw * (float)(j + 1);
            float nlo = (j > 0) ? (lo + stepw * (float)j) : lo;
            hi = nhi; lo = nlo;
        }
    }
    float lam2 = 0.5f * (lo + hi);
    float p = 0.1f - lam2;
    return (p > 0.f) ? (p / (float)B) : 0.f;
}

// ============================================================================
// Kernel 2: single-warp finalizer. Solves the (rare/never) listed matrices,
// writes out[0] = sum of penalties (0 when list empty; replaces memset),
// and resets g_cnt for the next graph replay.
// ============================================================================
__global__ void __launch_bounds__(32)
finalize_kernel(const float* __restrict__ E, float* __restrict__ out, int B)
{
    __shared__ __align__(16) float ssv[64], ssw[64], ssdd[64], ssee[64];
    const int lane = threadIdx.x;

    int n = *(volatile int*)&g_cnt;
    if (n > MAXB) n = MAXB;
    float acc = 0.f;
    for (int k = 0; k < n; k++) {
        int b = g_list[k];
        float p = solve_one_warp(E + (size_t)b * 4096, B, lane,
                                 ssv, ssw, ssdd, ssee);
        if (lane == 0) acc += p;
    }
    if (lane == 0) {
        out[0] = acc;
        g_cnt = 0;                 // leave-clean: next replay starts at 0
    }
}

extern "C" void kernel_launch(void* const* d_in, const int* in_sizes, int n_in,
                              void* d_out, int out_size)
{
    const float* E = (const float*)d_in[0];
    int B = in_sizes[0] / 4096;
    if (B > MAXB) B = MAXB;

    certify_kernel<<<B, 128>>>(E, B);
    finalize_kernel<<<1, 32>>>(E, (float*)d_out, B);
}

// round 15
// speedup vs baseline: 1.0757x; 1.0334x over previous
#include <cuda_runtime.h>
#include <cuda_bf16.h>
#include <math.h>

__device__ __forceinline__ float sg(float x) { return 1.f / (1.f + __expf(-x)); }

// ============================================================================
// Cold path: CTA-wide exact penalty via LDL-inertia bisection.
// Matrix lives in SHARED memory, loops are unroll-1, dynamic indexing
// => very low register use, so the hot path's regalloc is not disturbed.
// Executed essentially never (only when the certificate fails).
//
// count(x) = # eigenvalues of M below x = # negative pivots of LDL(M - xI).
// M = lower-symmetrized (diag(deg) - sigmoid(E)), deg from FULL sigmoid rows,
// matching eigvalsh's UPLO='L' view. Bisect lambda_2 in [-64, 0.1]
// (all |M_ij| <= 1 off-diag, M_ii >= -1 => Gershgorin lo >= -64).
// ============================================================================
__device__ __noinline__ int ldl_count(const float* __restrict__ Eb, float x,
                                      float (*A)[65], int t)
{
    if (t < 64) {
        float deg = 0.f, st = 0.f;
        #pragma unroll 1
        for (int j = 0; j < 64; j++) {
            float s = sg(Eb[t * 64 + j]);
            deg += s;
            if (j < t) { A[t][j] = -s; A[j][t] = -s; }   // unique writers
            if (j == t) st = s;
        }
        A[t][t] = deg - st - x;
    }
    __syncthreads();

    int cnt = 0;
    #pragma unroll 1
    for (int k = 0; k < 64; k++) {
        float p = A[k][k];
        float pg = (fabsf(p) < 1e-25f) ? ((p < 0.f) ? -1e-25f : 1e-25f) : p;
        cnt += (pg < 0.f) ? 1 : 0;                       // same on all threads
        if (t < 64 && t > k) {
            float f = A[t][k] / pg;
            #pragma unroll 1
            for (int j = k + 1; j < 64; j++)
                A[t][j] -= f * A[k][j];                  // row k is read-only here
        }
        __syncthreads();
    }
    return cnt;
}

__device__ __noinline__ void cta_exact_penalty(const float* __restrict__ Eb,
                                               float* __restrict__ out, int B,
                                               float (*A)[65], int t)
{
    int c = ldl_count(Eb, 0.1f, A, t);
    if (c < 2) return;                    // lambda_2 >= 0.1: contributes 0

    float lo = -64.f, hi = 0.1f;
    #pragma unroll 1
    for (int it = 0; it < 40; it++) {
        float mid = 0.5f * (lo + hi);
        int cm = ldl_count(Eb, mid, A, t);
        if (cm >= 2) hi = mid; else lo = mid;
    }
    if (t == 0) {
        float lam2 = 0.5f * (lo + hi);
        float p = 0.1f - lam2;
        if (p > 0.f) atomicAdd(out, p / (float)B);
    }
}

// ============================================================================
// Fused kernel: transcendental-free certificate that lambda_2 >= 0.1.
//
// M = lower-symmetrized (diag(deg) - sigmoid(E));  P = (M-0.1I) + 0.5*ones*ones^T.
// lambda_1(P) <= lambda_2(M - 0.1I)  (positive rank-1 interlacing).
// Gershgorin row bound on P with piecewise-linear sigmoid bounds:
//   deg_t >= sum_j clamp(0.5 + E[t][j]/4, 0, 0.5)
//   |0.5 - sigma(x)| <= min(|x|/4, 0.5),  sigma_tt <= 1
// min_t bound_t >= 0 (with fp slack) => this matrix contributes exactly 0.
// Otherwise the SAME CTA runs the smem LDL bisection solver (cold, reg-light).
//
// Shared memory is a single 16.6KB buffer: certify overlays its small scratch
// (colP 2KB / rowB / warpmin) on the region the cold solver later reuses as
// the full 64x65 matrix.
// ============================================================================
__global__ void __launch_bounds__(128, 9)
spectral_kernel(const float* __restrict__ E, float* __restrict__ out, int B)
{
    const int b = blockIdx.x;
    if (b >= B) return;
    const int t  = threadIdx.x;
    const int q  = t & 15;     // column quad: columns 4q..4q+3
    const int g  = t >> 4;     // row group 0..7: rows 8i+g
    const int c0 = 4 * q;

    __shared__ __align__(16) float SB[64 * 65];   // union: certify scratch / solver matrix
    __shared__ int sneed;

    float (*colP)[64]   = (float(*)[64])SB;       // [8][64]  = 512 floats
    float* rowB         = SB + 512;               // 64 floats
    float* warpmin      = SB + 576;               // 4 floats

    const float4* E4 = (const float4*)(E + (size_t)b * 4096);

    float e[8];                      // per-row-i: degterm - rowrad partials
    float col0 = 0.f, col1 = 0.f, col2 = 0.f, col3 = 0.f;

    #pragma unroll
    for (int h = 0; h < 2; h++) {
        float4 v[4];
        #pragma unroll
        for (int u = 0; u < 4; u++) v[u] = E4[(4 * h + u) * 128 + t];  // MLP=4
        #pragma unroll
        for (int u = 0; u < 4; u++) {
            const int i = 4 * h + u;
            const int r = 8 * i + g;
            float acc = 0.f, uu, m;

            uu = 0.25f * v[u].x;
            acc += fminf(fmaxf(uu + 0.5f, 0.f), 0.5f);
            m = fminf(fabsf(uu), 0.5f);
            if (r > c0 + 0) { acc -= m; col0 += m; }

            uu = 0.25f * v[u].y;
            acc += fminf(fmaxf(uu + 0.5f, 0.f), 0.5f);
            m = fminf(fabsf(uu), 0.5f);
            if (r > c0 + 1) { acc -= m; col1 += m; }

            uu = 0.25f * v[u].z;
            acc += fminf(fmaxf(uu + 0.5f, 0.f), 0.5f);
            m = fminf(fabsf(uu), 0.5f);
            if (r > c0 + 2) { acc -= m; col2 += m; }

            uu = 0.25f * v[u].w;
            acc += fminf(fmaxf(uu + 0.5f, 0.f), 0.5f);
            m = fminf(fabsf(uu), 0.5f);
            if (r > c0 + 3) { acc -= m; col3 += m; }

            e[i] = acc;
        }
    }

    // Butterfly over the 16 q-lanes (xor<16 stays within the half-warp = one g)
    #pragma unroll
    for (int o = 1; o < 16; o <<= 1) {
        #pragma unroll
        for (int i = 0; i < 8; i++)
            e[i] += __shfl_xor_sync(0xffffffffu, e[i], o);
    }

    // Lane q<8 publishes row 8q+g (static-index select from e[])
    if (q < 8) {
        float es = 0.f;
        #pragma unroll
        for (int i = 0; i < 8; i++)
            if (q == i) es = e[i];
        rowB[8 * q + g] = es - 0.6f;
    }
    colP[g][c0 + 0] = col0;
    colP[g][c0 + 1] = col1;
    colP[g][c0 + 2] = col2;
    colP[g][c0 + 3] = col3;
    __syncthreads();

    float bound = 1e30f;
    if (t < 64) {
        float cs = 0.f;
        #pragma unroll
        for (int gg = 0; gg < 8; gg++) cs += colP[gg][t];
        bound = rowB[t] - cs;
    }
    #pragma unroll
    for (int o = 16; o > 0; o >>= 1)
        bound = fminf(bound, __shfl_xor_sync(0xffffffffu, bound, o));
    if ((t & 31) == 0) warpmin[t >> 5] = bound;
    __syncthreads();
    if (t == 0) {
        float mn = fminf(fminf(warpmin[0], warpmin[1]),
                         fminf(warpmin[2], warpmin[3]));
        sneed = (mn < 0.05f) ? 1 : 0;        // 0.05 = fp-rounding slack
    }
    __syncthreads();

    // Cold path: exact solve by this CTA (certificate failed; essentially never).
    if (sneed) {
        cta_exact_penalty(E + (size_t)b * 4096, out, B, (float(*)[65])SB, t);
    }
}

extern "C" void kernel_launch(void* const* d_in, const int* in_sizes, int n_in,
                              void* d_out, int out_size)
{
    const float* E = (const float*)d_in[0];
    int B = in_sizes[0] / 4096;

    cudaMemsetAsync(d_out, 0, sizeof(float));   // out = 0; rare path adds terms
    spectral_kernel<<<B, 128>>>(E, (float*)d_out, B);
}

// round 16
// speedup vs baseline: 1.0977x; 1.0205x over previous
#include <cuda_runtime.h>
#include <cuda_bf16.h>
#include <math.h>

__device__ __forceinline__ float sg(float x) { return 1.f / (1.f + __expf(-x)); }

// ============================================================================
// Cold path: CTA-wide exact penalty via LDL-inertia bisection.
// Matrix lives in SHARED memory, loops are unroll-1, dynamic indexing
// => very low register use, so the hot path's regalloc is not disturbed.
// Executed essentially never (only when the certificate fails).
//
// count(x) = # eigenvalues of M below x = # negative pivots of LDL(M - xI).
// M = lower-symmetrized (diag(deg) - sigmoid(E)), matching eigvalsh UPLO='L'.
// Bisect lambda_2 in [-64, 0.1].
// ============================================================================
__device__ __noinline__ int ldl_count(const float* __restrict__ Eb, float x,
                                      float (*A)[65], int t)
{
    if (t < 64) {
        float deg = 0.f, st = 0.f;
        #pragma unroll 1
        for (int j = 0; j < 64; j++) {
            float s = sg(Eb[t * 64 + j]);
            deg += s;
            if (j < t) { A[t][j] = -s; A[j][t] = -s; }   // unique writers
            if (j == t) st = s;
        }
        A[t][t] = deg - st - x;
    }
    __syncthreads();

    int cnt = 0;
    #pragma unroll 1
    for (int k = 0; k < 64; k++) {
        float p = A[k][k];
        float pg = (fabsf(p) < 1e-25f) ? ((p < 0.f) ? -1e-25f : 1e-25f) : p;
        cnt += (pg < 0.f) ? 1 : 0;                       // same on all threads
        if (t < 64 && t > k) {
            float f = A[t][k] / pg;
            #pragma unroll 1
            for (int j = k + 1; j < 64; j++)
                A[t][j] -= f * A[k][j];                  // row k read-only here
        }
        __syncthreads();
    }
    return cnt;
}

__device__ __noinline__ void cta_exact_penalty(const float* __restrict__ Eb,
                                               float* __restrict__ out, int B,
                                               float (*A)[65], int t)
{
    int c = ldl_count(Eb, 0.1f, A, t);
    if (c < 2) return;                    // lambda_2 >= 0.1: contributes 0

    float lo = -64.f, hi = 0.1f;
    #pragma unroll 1
    for (int it = 0; it < 40; it++) {
        float mid = 0.5f * (lo + hi);
        int cm = ldl_count(Eb, mid, A, t);
        if (cm >= 2) hi = mid; else lo = mid;
    }
    if (t == 0) {
        float lam2 = 0.5f * (lo + hi);
        float p = 0.1f - lam2;
        if (p > 0.f) atomicAdd(out, p / (float)B);
    }
}

// ============================================================================
// Fused kernel: transcendental-free certificate that lambda_2 >= 0.1.
//
// M = lower-symmetrized (diag(deg) - sigmoid(E));  P = (M-0.1I) + 0.5*ones*ones^T.
// lambda_1(P) <= lambda_2(M - 0.1I)  (positive rank-1 interlacing).
// Gershgorin on P with UNCAPPED tangent bounds (sigmoid convex on x<0):
//   sigma(x) >= 0.5 + min(x/4, 0)        => deg_t >= 32 + sum_j 0.125*(x - |x|)
//   |sigma(x) - 0.5| <= |x|/4            => radius terms 0.25*|x|
//   sigma_tt <= 1
// bound_t = 32 + E_t - 0.6 - 0.25*C_t,
//   E_t = sum_j [0.125(x-|x|) - 0.25|x|*[r>c]] over row t,
//   C_t = sum over column t of |x| from rows r>t.
// min_t bound_t >= 0 (with fp slack) => this matrix contributes exactly 0.
// Otherwise the SAME CTA runs the smem LDL bisection solver (cold, reg-light).
// Per element: 1 FADD + 1 FFMA + ISETP + 2 predicated ops (|x| is a modifier).
// ============================================================================
__global__ void __launch_bounds__(128, 10)
spectral_kernel(const float* __restrict__ E, float* __restrict__ out, int B)
{
    const int b = blockIdx.x;
    if (b >= B) return;
    const int t  = threadIdx.x;
    const int q  = t & 15;     // column quad: columns 4q..4q+3
    const int g  = t >> 4;     // row group 0..7: rows 8i+g
    const int c0 = 4 * q;

    __shared__ __align__(16) float SB[64 * 65];   // union: certify scratch / solver matrix
    __shared__ int sneed;

    float (*colP)[64]   = (float(*)[64])SB;       // [8][64]  = 512 floats
    float* rowB         = SB + 512;               // 64 floats
    float* warpmin      = SB + 576;               // 4 floats

    const float4* E4 = (const float4*)(E + (size_t)b * 4096);

    float e[8];                      // per-row-i combined deg/row-rad partials
    #pragma unroll
    for (int i = 0; i < 8; i++) e[i] = 0.f;
    float col0 = 0.f, col1 = 0.f, col2 = 0.f, col3 = 0.f;

    #pragma unroll
    for (int h = 0; h < 2; h++) {
        float4 v[4];
        #pragma unroll
        for (int u = 0; u < 4; u++) v[u] = E4[(4 * h + u) * 128 + t];  // MLP=4
        #pragma unroll
        for (int u = 0; u < 4; u++) {
            const int i = 4 * h + u;
            const int r = 8 * i + g;
            float xx, ax;

            xx = v[u].x; ax = fabsf(xx);
            e[i] = fmaf(0.125f, xx - ax, e[i]);
            if (r > c0 + 0) { e[i] = fmaf(-0.25f, ax, e[i]); col0 += ax; }

            xx = v[u].y; ax = fabsf(xx);
            e[i] = fmaf(0.125f, xx - ax, e[i]);
            if (r > c0 + 1) { e[i] = fmaf(-0.25f, ax, e[i]); col1 += ax; }

            xx = v[u].z; ax = fabsf(xx);
            e[i] = fmaf(0.125f, xx - ax, e[i]);
            if (r > c0 + 2) { e[i] = fmaf(-0.25f, ax, e[i]); col2 += ax; }

            xx = v[u].w; ax = fabsf(xx);
            e[i] = fmaf(0.125f, xx - ax, e[i]);
            if (r > c0 + 3) { e[i] = fmaf(-0.25f, ax, e[i]); col3 += ax; }
        }
    }

    // Butterfly over the 16 q-lanes (xor<16 stays within the half-warp = one g)
    #pragma unroll
    for (int o = 1; o < 16; o <<= 1) {
        #pragma unroll
        for (int i = 0; i < 8; i++)
            e[i] += __shfl_xor_sync(0xffffffffu, e[i], o);
    }

    // Lane q<8 publishes row 8q+g: 32 (hoisted 0.5-sum) - 0.6 (slack) + E
    if (q < 8) {
        float es = 0.f;
        #pragma unroll
        for (int i = 0; i < 8; i++)
            if (q == i) es = e[i];
        rowB[8 * q + g] = es + 31.4f;
    }
    colP[g][c0 + 0] = col0;
    colP[g][c0 + 1] = col1;
    colP[g][c0 + 2] = col2;
    colP[g][c0 + 3] = col3;
    __syncthreads();

    float bound = 1e30f;
    if (t < 64) {
        float cs = 0.f;
        #pragma unroll
        for (int gg = 0; gg < 8; gg++) cs += colP[gg][t];
        bound = rowB[t] - 0.25f * cs;
    }
    #pragma unroll
    for (int o = 16; o > 0; o >>= 1)
        bound = fminf(bound, __shfl_xor_sync(0xffffffffu, bound, o));
    if ((t & 31) == 0) warpmin[t >> 5] = bound;
    __syncthreads();
    if (t == 0) {
        float mn = fminf(fminf(warpmin[0], warpmin[1]),
                         fminf(warpmin[2], warpmin[3]));
        sneed = (mn < 0.05f) ? 1 : 0;        // 0.05 = fp-rounding slack
    }
    __syncthreads();

    // Cold path: exact solve by this CTA (certificate failed; essentially never).
    if (sneed) {
        cta_exact_penalty(E + (size_t)b * 4096, out, B, (float(*)[65])SB, t);
    }
}

extern "C" void kernel_launch(void* const* d_in, const int* in_sizes, int n_in,
                              void* d_out, int out_size)
{
    const float* E = (const float*)d_in[0];
    int B = in_sizes[0] / 4096;

    cudaMemsetAsync(d_out, 0, sizeof(float));   // out = 0; rare path adds terms
    spectral_kernel<<<B, 128>>>(E, (float*)d_out, B);
}